// round 14
// baseline (speedup 1.0000x reference)
#include <cuda_runtime.h>
#include <cuda_fp16.h>
#include <math.h>
#include <stdint.h>

#define SEQ 4096
#define DIM 1024

// ======================= device scratch (no cudaMalloc) ====================
__device__ float  g_S[(size_t)SEQ * SEQ];                    // scores fp32
__device__ __half g_xh[(size_t)SEQ * DIM],  g_xl[(size_t)SEQ * DIM];
__device__ __half g_wqh[(size_t)DIM * DIM], g_wql[(size_t)DIM * DIM];
__device__ __half g_wkh[(size_t)DIM * DIM], g_wkl[(size_t)DIM * DIM];
__device__ __half g_wvh[(size_t)DIM * DIM], g_wvl[(size_t)DIM * DIM];
__device__ __half g_qh[(size_t)SEQ * DIM],  g_ql[(size_t)SEQ * DIM];
__device__ __half g_kh[(size_t)SEQ * DIM],  g_kl[(size_t)SEQ * DIM];
__device__ __half g_vth[(size_t)DIM * SEQ];                  // V^T fp16
__device__ __half g_ph[(size_t)SEQ * SEQ];                   // probs fp16

// ======================= helpers ===========================================
__device__ __forceinline__ uint32_t smem_u32(const void* p) {
    uint32_t a;
    asm("{ .reg .u64 t; cvta.to.shared.u64 t, %1; cvt.u32.u64 %0, t; }"
        : "=r"(a) : "l"(p));
    return a;
}
__device__ __forceinline__ void cpasync16(uint32_t dst, const void* src) {
    asm volatile("cp.async.cg.shared.global [%0], [%1], 16;"
                 :: "r"(dst), "l"(src));
}
#define CP_COMMIT() asm volatile("cp.async.commit_group;" ::: "memory")
#define CP_WAIT(n)  asm volatile("cp.async.wait_group %0;" :: "n"(n) : "memory")

#define LDSM4(r0, r1, r2, r3, addr)                                          \
    asm volatile("ldmatrix.sync.aligned.m8n8.x4.shared.b16 {%0,%1,%2,%3}, [%4];" \
                 : "=r"(r0), "=r"(r1), "=r"(r2), "=r"(r3) : "r"(addr))

#define MMAF16(c, a0, a1, a2, a3, b0, b1)                                    \
    asm volatile("mma.sync.aligned.m16n8k16.row.col.f32.f16.f16.f32 "        \
                 "{%0,%1,%2,%3}, {%4,%5,%6,%7}, {%8,%9}, {%0,%1,%2,%3};"     \
                 : "+f"((c)[0]), "+f"((c)[1]), "+f"((c)[2]), "+f"((c)[3])    \
                 : "r"(a0), "r"(a1), "r"(a2), "r"(a3), "r"(b0), "r"(b1))

__device__ __forceinline__ void split2h(float v, __half& h, __half& l) {
    h = __float2half_rn(v);
    l = __float2half_rn(v - __half2float(h));
}

// fast 2^y for y <= 0 on the FMA/ALU pipes (no MUFU). rel err < 2e-5.
__device__ __forceinline__ float exp2p(float y) {
    y = fmaxf(y, -80.0f);
    float k = floorf(y);
    float f = y - k;
    float p = 1.540353e-4f;
    p = fmaf(p, f, 1.3333558e-3f);
    p = fmaf(p, f, 9.6181291e-3f);
    p = fmaf(p, f, 5.5504109e-2f);
    p = fmaf(p, f, 2.4022650e-1f);
    p = fmaf(p, f, 6.9314718e-1f);
    p = fmaf(p, f, 1.0f);
    return p * __int_as_float(((int)k + 127) << 23);
}
#define LOG2E 1.4426950408889634f

// ======================= GEMM: C[M,N] = alpha*(A @ B^T) + bias =============
// TERMS=3 template supports a RUNTIME per-z 'aspl' flag: aspl=1 computes
// A1B1+A1B2+A2B1; aspl=0 computes A1B1+A1B2 (A2 region unused).
// TERMS=1: A1B1 only.  CTA tile 128x128, 128 threads = 4 warps (2x2),
// warp tile 64x64, BK=32/chunk, CPS chunks/stage, SW64 swizzle, 3-stage
// cp.async pipeline, 2 CTAs/SM.
enum { EPI_F32 = 0, EPI_SPLIT = 1, EPI_H_T = 3 };

struct GArgs {
    const __half* A1[3];
    const __half* A2[3];
    const __half* B1[3];
    const __half* B2[3];
    const float*  bias[3];
    float*        Cf[3];
    __half*       Ch[3];
    __half*       Cl[3];
    int           epi[3];
    int           aspl[3];
    int           N[3];
    float         alpha[3];
    int K, ldct;
};

__device__ __forceinline__ uint32_t sw64(uint32_t r, uint32_t c16) {
    return r * 64 + (((c16 ^ ((r >> 1) & 3)) & 3) << 4);
}

template <int TERMS, int CPS>
__global__ __launch_bounds__(128, 2)
void gemm_mma(const GArgs ga) {
    constexpr bool HASA2 = (TERMS == 3);
    constexpr bool BSPL = (TERMS >= 2);
    constexpr uint32_t R_SZ = 8192;
    constexpr uint32_t OFF_A2 = R_SZ;
    constexpr uint32_t OFF_B1 = HASA2 ? 2 * R_SZ : R_SZ;
    constexpr uint32_t OFF_B2 = OFF_B1 + R_SZ;
    constexpr uint32_t CHUNK = OFF_B1 + (BSPL ? 2 : 1) * R_SZ;
    constexpr uint32_t STG = CPS * CHUNK;

    extern __shared__ char smem[];
    const uint32_t sb = smem_u32(smem);
    const int tid = threadIdx.x;
    const int lane = tid & 31;
    const int w = tid >> 5;
    const int wm = w >> 1;
    const int wn = w & 1;
    const int z = blockIdx.z;
    const int row0 = blockIdx.y * 128;
    const int col0 = blockIdx.x * 128;

    const __half* __restrict__ A1 = ga.A1[z];
    const __half* __restrict__ A2 = ga.A2[z];
    const __half* __restrict__ B1g = ga.B1[z];
    const __half* __restrict__ B2g = ga.B2[z];
    const int K = ga.K;
    const bool aspl = HASA2 && (ga.aspl[z] != 0);

    float acc[4][8][4] = {};
    const int nst = (K >> 5) / CPS;

    auto load_stage = [&](int slot, int st) {
        uint32_t s0 = sb + (uint32_t)slot * STG;
#pragma unroll
        for (int h = 0; h < CPS; h++) {
            int k0 = (st * CPS + h) << 5;
            uint32_t c0 = s0 + h * CHUNK;
#pragma unroll
            for (int p = 0; p < 4; p++) {
                int idx = tid + p * 128;
                uint32_t r = idx >> 2, c = idx & 3;
                uint32_t d = c0 + sw64(r, c);
                size_t gA = (size_t)(row0 + r) * K + k0 + c * 8;
                size_t gB = (size_t)(col0 + r) * K + k0 + c * 8;
                cpasync16(d, A1 + gA);
                if (aspl) cpasync16(d + OFF_A2, A2 + gA);
                cpasync16(d + OFF_B1, B1g + gB);
                if (BSPL) cpasync16(d + OFF_B2, B2g + gB);
            }
        }
    };

    const uint32_t r0a = (lane & 7) + ((lane >> 3) & 1) * 8 + wm * 64;
    const uint32_t swa = ((r0a >> 1) & 3) << 4;
    const uint32_t aoff = r0a * 64 + ((((lane >> 4) & 1) << 4) ^ swa);
    const uint32_t r0b = (lane & 7) + ((lane >> 4) & 1) * 8 + wn * 64;
    const uint32_t swb = ((r0b >> 1) & 3) << 4;
    const uint32_t boff = r0b * 64 + ((((lane >> 3) & 1) << 4) ^ swb);

    load_stage(0, 0);
    CP_COMMIT();
    load_stage(1, 1);
    CP_COMMIT();

    int slot = 0;
    for (int st = 0; st < nst; st++) {
        CP_WAIT(1);
        __syncthreads();
        if (st + 2 < nst) {
            int ns = slot + 2; if (ns >= 3) ns -= 3;
            load_stage(ns, st + 2);
        }
        CP_COMMIT();

#pragma unroll
        for (int h = 0; h < CPS; h++) {
            const uint32_t s0 = sb + (uint32_t)slot * STG + h * CHUNK;
            const uint32_t aB = s0 + aoff;
            const uint32_t bB = s0 + OFF_B1 + boff;
#pragma unroll
            for (int ks = 0; ks < 2; ks++) {
                uint32_t a1[4][4], a2[4][4];
#pragma unroll
                for (int mi = 0; mi < 4; mi++) {
                    uint32_t a = (aB + mi * 1024) ^ (ks << 5);
                    LDSM4(a1[mi][0], a1[mi][1], a1[mi][2], a1[mi][3], a);
                    if (aspl) LDSM4(a2[mi][0], a2[mi][1], a2[mi][2], a2[mi][3],
                                    a + OFF_A2);
                }
                uint32_t b1[8][2], b2[8][2];
#pragma unroll
                for (int j = 0; j < 4; j++) {
                    uint32_t b = (bB + j * 1024) ^ (ks << 5);
                    LDSM4(b1[2 * j][0], b1[2 * j][1], b1[2 * j + 1][0],
                          b1[2 * j + 1][1], b);
                    if (BSPL)
                        LDSM4(b2[2 * j][0], b2[2 * j][1], b2[2 * j + 1][0],
                              b2[2 * j + 1][1], b + R_SZ);
                }
#pragma unroll
                for (int mi = 0; mi < 4; mi++)
#pragma unroll
                    for (int ni = 0; ni < 8; ni++) {
                        MMAF16(acc[mi][ni], a1[mi][0], a1[mi][1], a1[mi][2],
                               a1[mi][3], b1[ni][0], b1[ni][1]);
                        if (BSPL)
                            MMAF16(acc[mi][ni], a1[mi][0], a1[mi][1], a1[mi][2],
                                   a1[mi][3], b2[ni][0], b2[ni][1]);
                        if (aspl)
                            MMAF16(acc[mi][ni], a2[mi][0], a2[mi][1], a2[mi][2],
                                   a2[mi][3], b1[ni][0], b1[ni][1]);
                    }
            }
        }
        slot++; if (slot >= 3) slot = 0;
    }

    CP_WAIT(0);
    __syncthreads();

    const int tr = lane >> 2;
    const int tc = (lane & 3) * 2;
    const int epi = ga.epi[z];
    const float* bias = ga.bias[z];
    const float alpha = ga.alpha[z];

    if (epi == EPI_H_T) {
        __half* __restrict__ Ch = ga.Ch[z];
        float* T = reinterpret_cast<float*>(smem);   // [128][133]
#pragma unroll
        for (int mi = 0; mi < 4; mi++)
#pragma unroll
            for (int ni = 0; ni < 8; ni++) {
                int r = wm * 64 + mi * 16 + tr;
                int c = wn * 64 + ni * 8 + tc;
                T[r * 133 + c]           = acc[mi][ni][0];
                T[r * 133 + c + 1]       = acc[mi][ni][1];
                T[(r + 8) * 133 + c]     = acc[mi][ni][2];
                T[(r + 8) * 133 + c + 1] = acc[mi][ni][3];
            }
        __syncthreads();
        const int m = tid;
#pragma unroll 1
        for (int n = 0; n < 128; n++) {
            float v = T[m * 133 + n] * alpha + bias[col0 + n];
            Ch[(size_t)(col0 + n) * ga.ldct + row0 + m] = __float2half_rn(v);
        }
    } else if (epi == EPI_SPLIT) {
        __half* __restrict__ Ch = ga.Ch[z];
        __half* __restrict__ Cl = ga.Cl[z];
        const int N = ga.N[z];
#pragma unroll
        for (int mi = 0; mi < 4; mi++)
#pragma unroll
            for (int ni = 0; ni < 8; ni++) {
                int r = row0 + wm * 64 + mi * 16 + tr;
                int c = col0 + wn * 64 + ni * 8 + tc;
#pragma unroll
                for (int hh = 0; hh < 2; hh++) {
                    int rr = r + hh * 8;
                    float v0 = acc[mi][ni][2 * hh + 0] * alpha + bias[c];
                    float v1 = acc[mi][ni][2 * hh + 1] * alpha + bias[c + 1];
                    __half h0, l0, h1, l1;
                    split2h(v0, h0, l0);
                    split2h(v1, h1, l1);
                    *reinterpret_cast<__half2*>(&Ch[(size_t)rr * N + c]) =
                        __halves2half2(h0, h1);
                    *reinterpret_cast<__half2*>(&Cl[(size_t)rr * N + c]) =
                        __halves2half2(l0, l1);
                }
            }
    } else {  // EPI_F32
        float* __restrict__ Cf = ga.Cf[z];
        const int N = ga.N[z];
#pragma unroll
        for (int mi = 0; mi < 4; mi++)
#pragma unroll
            for (int ni = 0; ni < 8; ni++) {
                int r = row0 + wm * 64 + mi * 16 + tr;
                int c = col0 + wn * 64 + ni * 8 + tc;
#pragma unroll
                for (int hh = 0; hh < 2; hh++) {
                    int rr = r + hh * 8;
                    float2 f2 = make_float2(acc[mi][ni][2 * hh + 0] * alpha,
                                            acc[mi][ni][2 * hh + 1] * alpha);
                    *reinterpret_cast<float2*>(&Cf[(size_t)rr * N + c]) = f2;
                }
            }
    }
}

// ======================= elementwise split (x) =============================
__global__ __launch_bounds__(256)
void split_kernel(const float* __restrict__ in, __half* __restrict__ hi,
                  __half* __restrict__ lo, int n4) {
    int i = blockIdx.x * 256 + threadIdx.x;
    if (i >= n4) return;
    float4 v = reinterpret_cast<const float4*>(in)[i];
    __half h[4], l[4];
    split2h(v.x, h[0], l[0]);
    split2h(v.y, h[1], l[1]);
    split2h(v.z, h[2], l[2]);
    split2h(v.w, h[3], l[3]);
    reinterpret_cast<uint2*>(hi)[i] = *reinterpret_cast<uint2*>(h);
    reinterpret_cast<uint2*>(lo)[i] = *reinterpret_cast<uint2*>(l);
}

// ======================= split + transpose (3 W's, fused) ==================
struct TArgs {
    const float* in[3];
    __half* hiT[3];
    __half* loT[3];
};
__global__ __launch_bounds__(256)
void splitT3_kernel(const TArgs ta, int R, int C) {
    __shared__ float t[32][33];
    const int z = blockIdx.z;
    const float* __restrict__ in = ta.in[z];
    __half* __restrict__ hiT = ta.hiT[z];
    __half* __restrict__ loT = ta.loT[z];
    const int tx = threadIdx.x & 31, ty = threadIdx.x >> 5;
    const int bc = blockIdx.x * 32, br = blockIdx.y * 32;
#pragma unroll
    for (int j = 0; j < 4; j++)
        t[ty + 8 * j][tx] = in[(size_t)(br + ty + 8 * j) * C + bc + tx];
    __syncthreads();
#pragma unroll
    for (int j = 0; j < 4; j++) {
        int cc = ty + 8 * j;
        __half h, l;
        split2h(t[tx][cc], h, l);
        hiT[(size_t)(bc + cc) * R + br + tx] = h;
        loT[(size_t)(bc + cc) * R + br + tx] = l;
    }
}

// ======================= softmax: 128 thr/row, shuffle reductions ==========
__global__ __launch_bounds__(128)
void softmax_reg(const float* __restrict__ S, __half* __restrict__ ph, int n) {
    const int row = blockIdx.x;
    const int tid = threadIdx.x;
    const int lane = tid & 31;
    const int wid = tid >> 5;
    const float4* p = reinterpret_cast<const float4*>(S + (size_t)row * n);
    __shared__ float red[4];

    float4 q[8];                       // 32 values per thread
    float m = -INFINITY;
#pragma unroll
    for (int j = 0; j < 8; j++) {
        q[j] = p[tid + 128 * j];
        m = fmaxf(m, fmaxf(fmaxf(q[j].x, q[j].y), fmaxf(q[j].z, q[j].w)));
    }
#pragma unroll
    for (int off = 16; off > 0; off >>= 1)
        m = fmaxf(m, __shfl_xor_sync(0xffffffffu, m, off));
    if (lane == 0) red[wid] = m;
    __syncthreads();
    m = fmaxf(fmaxf(red[0], red[1]), fmaxf(red[2], red[3]));

    const float mlog = m * LOG2E;
    float sum = 0.0f;
#pragma unroll
    for (int j = 0; j < 8; j++) {
        q[j].x = exp2p(fmaf(q[j].x, LOG2E, -mlog));
        q[j].y = exp2p(fmaf(q[j].y, LOG2E, -mlog));
        q[j].z = exp2p(fmaf(q[j].z, LOG2E, -mlog));
        q[j].w = exp2p(fmaf(q[j].w, LOG2E, -mlog));
        sum += (q[j].x + q[j].y) + (q[j].z + q[j].w);
    }
#pragma unroll
    for (int off = 16; off > 0; off >>= 1)
        sum += __shfl_xor_sync(0xffffffffu, sum, off);
    __syncthreads();                   // red reuse
    if (lane == 0) red[wid] = sum;
    __syncthreads();
    const float inv = 1.0f / (((red[0] + red[1]) + (red[2] + red[3])));

    uint2* outp = reinterpret_cast<uint2*>(ph + (size_t)row * n);
#pragma unroll
    for (int j = 0; j < 8; j++) {
        __half h[4];
        h[0] = __float2half_rn(q[j].x * inv);
        h[1] = __float2half_rn(q[j].y * inv);
        h[2] = __float2half_rn(q[j].z * inv);
        h[3] = __float2half_rn(q[j].w * inv);
        outp[tid + 128 * j] = *reinterpret_cast<uint2*>(h);
    }
}

// ======================= launch ============================================
extern "C" void kernel_launch(void* const* d_in, const int* in_sizes, int n_in,
                              void* d_out, int out_size) {
    const float* x  = (const float*)d_in[0];
    const float* WQ = (const float*)d_in[1];
    const float* WK = (const float*)d_in[2];
    const float* WV = (const float*)d_in[3];
    const float* bQ = (const float*)d_in[4];
    const float* bK = (const float*)d_in[5];
    const float* bV = (const float*)d_in[6];
    float* out = (float*)d_out;

    float* S;
    __half *xh, *xl, *wqh, *wql, *wkh, *wkl, *wvh, *wvl;
    __half *qh, *ql, *kh, *kl, *vth, *ph;
    cudaGetSymbolAddress((void**)&S, g_S);
    cudaGetSymbolAddress((void**)&xh, g_xh);   cudaGetSymbolAddress((void**)&xl, g_xl);
    cudaGetSymbolAddress((void**)&wqh, g_wqh); cudaGetSymbolAddress((void**)&wql, g_wql);
    cudaGetSymbolAddress((void**)&wkh, g_wkh); cudaGetSymbolAddress((void**)&wkl, g_wkl);
    cudaGetSymbolAddress((void**)&wvh, g_wvh); cudaGetSymbolAddress((void**)&wvl, g_wvl);
    cudaGetSymbolAddress((void**)&qh, g_qh);   cudaGetSymbolAddress((void**)&ql, g_ql);
    cudaGetSymbolAddress((void**)&kh, g_kh);   cudaGetSymbolAddress((void**)&kl, g_kl);
    cudaGetSymbolAddress((void**)&vth, g_vth);
    cudaGetSymbolAddress((void**)&ph, g_ph);

    constexpr int SM_3T = 3 * 32768;   // TERMS=3 layout, CPS=1 -> 2 CTAs/SM
    constexpr int SM_1T = 3 * 32768;   // TERMS=1, CPS=2 -> 2 CTAs/SM

    cudaFuncSetAttribute((const void*)gemm_mma<3, 1>,
                         cudaFuncAttributeMaxDynamicSharedMemorySize, SM_3T);
    cudaFuncSetAttribute((const void*)gemm_mma<1, 2>,
                         cudaFuncAttributeMaxDynamicSharedMemorySize, SM_1T);

    // ---- prologue splits ----
    split_kernel<<<(SEQ * DIM / 4 + 255) / 256, 256>>>(x, xh, xl, SEQ * DIM / 4);
    {
        TArgs ta = {};
        ta.in[0] = WQ;  ta.in[1] = WK;  ta.in[2] = WV;
        ta.hiT[0] = wqh; ta.hiT[1] = wkh; ta.hiT[2] = wvh;
        ta.loT[0] = wql; ta.loT[1] = wkl; ta.loT[2] = wvl;
        dim3 gT(DIM / 32, DIM / 32, 3);
        splitT3_kernel<<<gT, 256>>>(ta, DIM, DIM);
    }

    // ---- unified QKV projections: Q,K 3-term (aspl=1), V 2-term (aspl=0) --
    {
        GArgs ga = {};
        for (int z = 0; z < 3; z++) { ga.A1[z] = xh; ga.A2[z] = xl; }
        ga.B1[0] = wqh; ga.B2[0] = wql;
        ga.B1[1] = wkh; ga.B2[1] = wkl;
        ga.B1[2] = wvh; ga.B2[2] = wvl;
        ga.bias[0] = bQ; ga.bias[1] = bK; ga.bias[2] = bV;
        ga.Ch[0] = qh; ga.Cl[0] = ql;
        ga.Ch[1] = kh; ga.Cl[1] = kl;
        ga.Ch[2] = vth;
        ga.epi[0] = EPI_SPLIT; ga.epi[1] = EPI_SPLIT; ga.epi[2] = EPI_H_T;
        ga.aspl[0] = 1; ga.aspl[1] = 1; ga.aspl[2] = 0;
        ga.N[0] = DIM; ga.N[1] = DIM; ga.N[2] = DIM;
        ga.alpha[0] = 1.0f; ga.alpha[1] = 1.0f; ga.alpha[2] = 1.0f;
        ga.K = DIM; ga.ldct = SEQ;
        dim3 g(DIM / 128, SEQ / 128, 3);
        gemm_mma<3, 1><<<g, 128, SM_3T>>>(ga);
    }

    // ---- scores: S = (Q @ K^T) / 32 (3-term) ----
    {
        GArgs ga = {};
        ga.A1[0] = qh; ga.A2[0] = ql;
        ga.B1[0] = kh; ga.B2[0] = kl;
        ga.Cf[0] = S; ga.epi[0] = EPI_F32;
        ga.aspl[0] = 1;
        ga.N[0] = SEQ; ga.alpha[0] = 0.03125f;
        ga.K = DIM; ga.ldct = 0;
        dim3 g(SEQ / 128, SEQ / 128, 1);
        gemm_mma<3, 1><<<g, 128, SM_3T>>>(ga);
    }

    // ---- softmax ----
    softmax_reg<<<SEQ, 128>>>(S, ph, SEQ);

    // ---- PV: out = P @ V ----
    {
        GArgs ga = {};
        ga.A1[0] = ph;
        ga.B1[0] = vth;
        ga.Cf[0] = out; ga.epi[0] = EPI_F32;
        ga.aspl[0] = 0;
        ga.N[0] = DIM; ga.alpha[0] = 1.0f;
        ga.K = SEQ; ga.ldct = 0;
        dim3 g(DIM / 128, SEQ / 128, 1);
        gemm_mma<1, 2><<<g, 128, SM_1T>>>(ga);
    }
}

// round 15
// speedup vs baseline: 1.0739x; 1.0739x over previous
#include <cuda_runtime.h>
#include <cuda_fp16.h>
#include <math.h>
#include <stdint.h>

#define SEQ 4096
#define DIM 1024

// ======================= device scratch (no cudaMalloc) ====================
__device__ float  g_S[(size_t)SEQ * SEQ];                    // scores fp32
__device__ __half g_xh[(size_t)SEQ * DIM],  g_xl[(size_t)SEQ * DIM];
__device__ __half g_wqh[(size_t)DIM * DIM], g_wql[(size_t)DIM * DIM];
__device__ __half g_wkh[(size_t)DIM * DIM], g_wkl[(size_t)DIM * DIM];
__device__ __half g_wvh[(size_t)DIM * DIM], g_wvl[(size_t)DIM * DIM];
__device__ __half g_qh[(size_t)SEQ * DIM],  g_ql[(size_t)SEQ * DIM];
__device__ __half g_kh[(size_t)SEQ * DIM],  g_kl[(size_t)SEQ * DIM];
__device__ __half g_vth[(size_t)DIM * SEQ];                  // V^T fp16
__device__ __half g_ph[(size_t)SEQ * SEQ];                   // probs fp16

// ======================= helpers ===========================================
__device__ __forceinline__ uint32_t smem_u32(const void* p) {
    uint32_t a;
    asm("{ .reg .u64 t; cvta.to.shared.u64 t, %1; cvt.u32.u64 %0, t; }"
        : "=r"(a) : "l"(p));
    return a;
}
__device__ __forceinline__ void cpasync16(uint32_t dst, const void* src) {
    asm volatile("cp.async.cg.shared.global [%0], [%1], 16;"
                 :: "r"(dst), "l"(src));
}
#define CP_COMMIT() asm volatile("cp.async.commit_group;" ::: "memory")
#define CP_WAIT(n)  asm volatile("cp.async.wait_group %0;" :: "n"(n) : "memory")

#define LDSM4(r0, r1, r2, r3, addr)                                          \
    asm volatile("ldmatrix.sync.aligned.m8n8.x4.shared.b16 {%0,%1,%2,%3}, [%4];" \
                 : "=r"(r0), "=r"(r1), "=r"(r2), "=r"(r3) : "r"(addr))

#define MMAF16(c, a0, a1, a2, a3, b0, b1)                                    \
    asm volatile("mma.sync.aligned.m16n8k16.row.col.f32.f16.f16.f32 "        \
                 "{%0,%1,%2,%3}, {%4,%5,%6,%7}, {%8,%9}, {%0,%1,%2,%3};"     \
                 : "+f"((c)[0]), "+f"((c)[1]), "+f"((c)[2]), "+f"((c)[3])    \
                 : "r"(a0), "r"(a1), "r"(a2), "r"(a3), "r"(b0), "r"(b1))

__device__ __forceinline__ void split2h(float v, __half& h, __half& l) {
    h = __float2half_rn(v);
    l = __float2half_rn(v - __half2float(h));
}

// fast 2^y on FMA/ALU pipes (no MUFU). rel err < 2e-5.
__device__ __forceinline__ float exp2p(float y) {
    y = fmaxf(y, -80.0f);
    float k = floorf(y);
    float f = y - k;
    float p = 1.540353e-4f;
    p = fmaf(p, f, 1.3333558e-3f);
    p = fmaf(p, f, 9.6181291e-3f);
    p = fmaf(p, f, 5.5504109e-2f);
    p = fmaf(p, f, 2.4022650e-1f);
    p = fmaf(p, f, 6.9314718e-1f);
    p = fmaf(p, f, 1.0f);
    return p * __int_as_float(((int)k + 127) << 23);
}
#define LOG2E 1.4426950408889634f

// ======================= GEMM: C[M,N] = alpha*(A @ B^T) + bias =============
// A [M,K] fp16 (split A1+A2 when TERMS=3), B [N,K] fp16 (split B1+B2 when
// TERMS>=2), K-major. CTA tile 128x128, 128 threads = 4 warps (2x2), warp
// tile 64x64. BK=32 per chunk, CPS chunks/stage, NSTAGE-deep cp.async
// pipeline, SW64-swizzled smem, 2 CTAs/SM. All term counts compile-time.
enum { EPI_F32 = 0, EPI_SPLIT = 1, EPI_H_T = 3 };

struct GArgs {
    const __half* A1[3];
    const __half* A2[3];
    const __half* B1[3];
    const __half* B2[3];
    const float*  bias[3];
    float*        Cf[3];
    __half*       Ch[3];
    __half*       Cl[3];
    int           epi[3];
    int           N[3];
    float         alpha[3];
    int K, ldct;
};

__device__ __forceinline__ uint32_t sw64(uint32_t r, uint32_t c16) {
    return r * 64 + (((c16 ^ ((r >> 1) & 3)) & 3) << 4);
}

template <int TERMS, int CPS, int NSTAGE>
__global__ __launch_bounds__(128, 2)
void gemm_mma(const GArgs ga) {
    constexpr bool ASPL = (TERMS == 3);
    constexpr bool BSPL = (TERMS >= 2);
    constexpr uint32_t R_SZ = 8192;
    constexpr uint32_t OFF_A2 = R_SZ;
    constexpr uint32_t OFF_B1 = ASPL ? 2 * R_SZ : R_SZ;
    constexpr uint32_t OFF_B2 = OFF_B1 + R_SZ;
    constexpr uint32_t CHUNK = OFF_B1 + (BSPL ? 2 : 1) * R_SZ;
    constexpr uint32_t STG = CPS * CHUNK;

    extern __shared__ char smem[];
    const uint32_t sb = smem_u32(smem);
    const int tid = threadIdx.x;
    const int lane = tid & 31;
    const int w = tid >> 5;             // 0..3
    const int wm = w >> 1;              // 0..1
    const int wn = w & 1;               // 0..1
    const int z = blockIdx.z;
    const int row0 = blockIdx.y * 128;
    const int col0 = blockIdx.x * 128;

    const __half* __restrict__ A1 = ga.A1[z];
    const __half* __restrict__ A2 = ga.A2[z];
    const __half* __restrict__ B1g = ga.B1[z];
    const __half* __restrict__ B2g = ga.B2[z];
    const int K = ga.K;

    float acc[4][8][4] = {};            // warp tile 64x64
    const int nst = (K >> 5) / CPS;

    auto load_stage = [&](int slot, int st) {
        uint32_t s0 = sb + (uint32_t)slot * STG;
#pragma unroll
        for (int h = 0; h < CPS; h++) {
            int k0 = (st * CPS + h) << 5;
            uint32_t c0 = s0 + h * CHUNK;
#pragma unroll
            for (int p = 0; p < 4; p++) {
                int idx = tid + p * 128;
                uint32_t r = idx >> 2, c = idx & 3;
                uint32_t d = c0 + sw64(r, c);
                size_t gA = (size_t)(row0 + r) * K + k0 + c * 8;
                size_t gB = (size_t)(col0 + r) * K + k0 + c * 8;
                cpasync16(d, A1 + gA);
                if (ASPL) cpasync16(d + OFF_A2, A2 + gA);
                cpasync16(d + OFF_B1, B1g + gB);
                if (BSPL) cpasync16(d + OFF_B2, B2g + gB);
            }
        }
    };

    const uint32_t r0a = (lane & 7) + ((lane >> 3) & 1) * 8 + wm * 64;
    const uint32_t swa = ((r0a >> 1) & 3) << 4;
    const uint32_t aoff = r0a * 64 + ((((lane >> 4) & 1) << 4) ^ swa);
    const uint32_t r0b = (lane & 7) + ((lane >> 4) & 1) * 8 + wn * 64;
    const uint32_t swb = ((r0b >> 1) & 3) << 4;
    const uint32_t boff = r0b * 64 + ((((lane >> 3) & 1) << 4) ^ swb);

    // preload NSTAGE-1 stages
#pragma unroll
    for (int s = 0; s < NSTAGE - 1; s++) {
        load_stage(s, s);
        CP_COMMIT();
    }

    int slot = 0;
    for (int st = 0; st < nst; st++) {
        CP_WAIT(NSTAGE - 2);
        __syncthreads();
        if (st + NSTAGE - 1 < nst) {
            int ns = slot + NSTAGE - 1; if (ns >= NSTAGE) ns -= NSTAGE;
            load_stage(ns, st + NSTAGE - 1);
        }
        CP_COMMIT();

#pragma unroll
        for (int h = 0; h < CPS; h++) {
            const uint32_t s0 = sb + (uint32_t)slot * STG + h * CHUNK;
            const uint32_t aB = s0 + aoff;
            const uint32_t bB = s0 + OFF_B1 + boff;
#pragma unroll
            for (int ks = 0; ks < 2; ks++) {
                uint32_t a1[4][4], a2[4][4];
#pragma unroll
                for (int mi = 0; mi < 4; mi++) {
                    uint32_t a = (aB + mi * 1024) ^ (ks << 5);
                    LDSM4(a1[mi][0], a1[mi][1], a1[mi][2], a1[mi][3], a);
                    if (ASPL) LDSM4(a2[mi][0], a2[mi][1], a2[mi][2], a2[mi][3],
                                    a + OFF_A2);
                }
                uint32_t b1[8][2], b2[8][2];
#pragma unroll
                for (int j = 0; j < 4; j++) {
                    uint32_t b = (bB + j * 1024) ^ (ks << 5);
                    LDSM4(b1[2 * j][0], b1[2 * j][1], b1[2 * j + 1][0],
                          b1[2 * j + 1][1], b);
                    if (BSPL)
                        LDSM4(b2[2 * j][0], b2[2 * j][1], b2[2 * j + 1][0],
                              b2[2 * j + 1][1], b + R_SZ);
                }
#pragma unroll
                for (int mi = 0; mi < 4; mi++)
#pragma unroll
                    for (int ni = 0; ni < 8; ni++) {
                        MMAF16(acc[mi][ni], a1[mi][0], a1[mi][1], a1[mi][2],
                               a1[mi][3], b1[ni][0], b1[ni][1]);
                        if (BSPL)
                            MMAF16(acc[mi][ni], a1[mi][0], a1[mi][1], a1[mi][2],
                                   a1[mi][3], b2[ni][0], b2[ni][1]);
                        if (ASPL)
                            MMAF16(acc[mi][ni], a2[mi][0], a2[mi][1], a2[mi][2],
                                   a2[mi][3], b1[ni][0], b1[ni][1]);
                    }
            }
        }
        slot++; if (slot >= NSTAGE) slot = 0;
    }

    CP_WAIT(0);
    __syncthreads();

    const int tr = lane >> 2;
    const int tc = (lane & 3) * 2;
    const int epi = ga.epi[z];
    const float* bias = ga.bias[z];
    const float alpha = ga.alpha[z];

    if (epi == EPI_H_T) {
        __half* __restrict__ Ch = ga.Ch[z];
        float* T = reinterpret_cast<float*>(smem);   // [128][133] = 68KB
#pragma unroll
        for (int mi = 0; mi < 4; mi++)
#pragma unroll
            for (int ni = 0; ni < 8; ni++) {
                int r = wm * 64 + mi * 16 + tr;
                int c = wn * 64 + ni * 8 + tc;
                T[r * 133 + c]           = acc[mi][ni][0];
                T[r * 133 + c + 1]       = acc[mi][ni][1];
                T[(r + 8) * 133 + c]     = acc[mi][ni][2];
                T[(r + 8) * 133 + c + 1] = acc[mi][ni][3];
            }
        __syncthreads();
        const int m = tid;               // 0..127
#pragma unroll 1
        for (int n = 0; n < 128; n++) {
            float v = T[m * 133 + n] * alpha + bias[col0 + n];
            Ch[(size_t)(col0 + n) * ga.ldct + row0 + m] = __float2half_rn(v);
        }
    } else if (epi == EPI_SPLIT) {
        __half* __restrict__ Ch = ga.Ch[z];
        __half* __restrict__ Cl = ga.Cl[z];
        const int N = ga.N[z];
#pragma unroll
        for (int mi = 0; mi < 4; mi++)
#pragma unroll
            for (int ni = 0; ni < 8; ni++) {
                int r = row0 + wm * 64 + mi * 16 + tr;
                int c = col0 + wn * 64 + ni * 8 + tc;
#pragma unroll
                for (int hh = 0; hh < 2; hh++) {
                    int rr = r + hh * 8;
                    float v0 = acc[mi][ni][2 * hh + 0] * alpha + bias[c];
                    float v1 = acc[mi][ni][2 * hh + 1] * alpha + bias[c + 1];
                    __half h0, l0, h1, l1;
                    split2h(v0, h0, l0);
                    split2h(v1, h1, l1);
                    *reinterpret_cast<__half2*>(&Ch[(size_t)rr * N + c]) =
                        __halves2half2(h0, h1);
                    *reinterpret_cast<__half2*>(&Cl[(size_t)rr * N + c]) =
                        __halves2half2(l0, l1);
                }
            }
    } else {  // EPI_F32
        float* __restrict__ Cf = ga.Cf[z];
        const int N = ga.N[z];
#pragma unroll
        for (int mi = 0; mi < 4; mi++)
#pragma unroll
            for (int ni = 0; ni < 8; ni++) {
                int r = row0 + wm * 64 + mi * 16 + tr;
                int c = col0 + wn * 64 + ni * 8 + tc;
#pragma unroll
                for (int hh = 0; hh < 2; hh++) {
                    int rr = r + hh * 8;
                    float2 f2 = make_float2(acc[mi][ni][2 * hh + 0] * alpha,
                                            acc[mi][ni][2 * hh + 1] * alpha);
                    *reinterpret_cast<float2*>(&Cf[(size_t)rr * N + c]) = f2;
                }
            }
    }
}

// ======================= elementwise split (x) =============================
__global__ __launch_bounds__(256)
void split_kernel(const float* __restrict__ in, __half* __restrict__ hi,
                  __half* __restrict__ lo, int n4) {
    int i = blockIdx.x * 256 + threadIdx.x;
    if (i >= n4) return;
    float4 v = reinterpret_cast<const float4*>(in)[i];
    __half h[4], l[4];
    split2h(v.x, h[0], l[0]);
    split2h(v.y, h[1], l[1]);
    split2h(v.z, h[2], l[2]);
    split2h(v.w, h[3], l[3]);
    reinterpret_cast<uint2*>(hi)[i] = *reinterpret_cast<uint2*>(h);
    reinterpret_cast<uint2*>(lo)[i] = *reinterpret_cast<uint2*>(l);
}

// ======================= split + transpose (3 W's, fused) ==================
struct TArgs {
    const float* in[3];
    __half* hiT[3];
    __half* loT[3];
};
__global__ __launch_bounds__(256)
void splitT3_kernel(const TArgs ta, int R, int C) {
    __shared__ float t[32][33];
    const int z = blockIdx.z;
    const float* __restrict__ in = ta.in[z];
    __half* __restrict__ hiT = ta.hiT[z];
    __half* __restrict__ loT = ta.loT[z];
    const int tx = threadIdx.x & 31, ty = threadIdx.x >> 5;
    const int bc = blockIdx.x * 32, br = blockIdx.y * 32;
#pragma unroll
    for (int j = 0; j < 4; j++)
        t[ty + 8 * j][tx] = in[(size_t)(br + ty + 8 * j) * C + bc + tx];
    __syncthreads();
#pragma unroll
    for (int j = 0; j < 4; j++) {
        int cc = ty + 8 * j;
        __half h, l;
        split2h(t[tx][cc], h, l);
        hiT[(size_t)(bc + cc) * R + br + tx] = h;
        loT[(size_t)(bc + cc) * R + br + tx] = l;
    }
}

// ======================= softmax: register-resident, polynomial exp ========
__global__ __launch_bounds__(256)
void softmax_reg(const float* __restrict__ S, __half* __restrict__ ph, int n) {
    const int row = blockIdx.x;
    const int tid = threadIdx.x;
    const float4* p = reinterpret_cast<const float4*>(S + (size_t)row * n);
    __shared__ float red[256];

    float v[16];
    float m = -INFINITY;
#pragma unroll
    for (int j = 0; j < 4; j++) {
        float4 q = p[tid + 256 * j];
        v[4 * j + 0] = q.x; v[4 * j + 1] = q.y;
        v[4 * j + 2] = q.z; v[4 * j + 3] = q.w;
        m = fmaxf(m, fmaxf(fmaxf(q.x, q.y), fmaxf(q.z, q.w)));
    }
    red[tid] = m;
    __syncthreads();
    for (int s = 128; s > 0; s >>= 1) {
        if (tid < s) red[tid] = fmaxf(red[tid], red[tid + s]);
        __syncthreads();
    }
    m = red[0];
    __syncthreads();

    const float mlog = m * LOG2E;
    float sum = 0.0f;
#pragma unroll
    for (int j = 0; j < 16; j++) {
        v[j] = exp2p(fmaf(v[j], LOG2E, -mlog));
        sum += v[j];
    }
    red[tid] = sum;
    __syncthreads();
    for (int s = 128; s > 0; s >>= 1) {
        if (tid < s) red[tid] += red[tid + s];
        __syncthreads();
    }
    const float inv = 1.0f / red[0];

    uint2* outp = reinterpret_cast<uint2*>(ph + (size_t)row * n);
#pragma unroll
    for (int j = 0; j < 4; j++) {
        __half h[4];
        h[0] = __float2half_rn(v[4 * j + 0] * inv);
        h[1] = __float2half_rn(v[4 * j + 1] * inv);
        h[2] = __float2half_rn(v[4 * j + 2] * inv);
        h[3] = __float2half_rn(v[4 * j + 3] * inv);
        outp[tid + 256 * j] = *reinterpret_cast<uint2*>(h);
    }
}

// ======================= launch ============================================
extern "C" void kernel_launch(void* const* d_in, const int* in_sizes, int n_in,
                              void* d_out, int out_size) {
    const float* x  = (const float*)d_in[0];
    const float* WQ = (const float*)d_in[1];
    const float* WK = (const float*)d_in[2];
    const float* WV = (const float*)d_in[3];
    const float* bQ = (const float*)d_in[4];
    const float* bK = (const float*)d_in[5];
    const float* bV = (const float*)d_in[6];
    float* out = (float*)d_out;

    float* S;
    __half *xh, *xl, *wqh, *wql, *wkh, *wkl, *wvh, *wvl;
    __half *qh, *ql, *kh, *kl, *vth, *ph;
    cudaGetSymbolAddress((void**)&S, g_S);
    cudaGetSymbolAddress((void**)&xh, g_xh);   cudaGetSymbolAddress((void**)&xl, g_xl);
    cudaGetSymbolAddress((void**)&wqh, g_wqh); cudaGetSymbolAddress((void**)&wql, g_wql);
    cudaGetSymbolAddress((void**)&wkh, g_wkh); cudaGetSymbolAddress((void**)&wkl, g_wkl);
    cudaGetSymbolAddress((void**)&wvh, g_wvh); cudaGetSymbolAddress((void**)&wvl, g_wvl);
    cudaGetSymbolAddress((void**)&qh, g_qh);   cudaGetSymbolAddress((void**)&ql, g_ql);
    cudaGetSymbolAddress((void**)&kh, g_kh);   cudaGetSymbolAddress((void**)&kl, g_kl);
    cudaGetSymbolAddress((void**)&vth, g_vth);
    cudaGetSymbolAddress((void**)&ph, g_ph);

    constexpr int SM_QK = 3 * 32768;   // TERMS=3, CPS=1, NSTAGE=3 -> 96KB
    constexpr int SM_V  = 4 * 24576;   // TERMS=2, CPS=1, NSTAGE=4 -> 96KB
    constexpr int SM_PV = 6 * 16384;   // TERMS=1, CPS=1, NSTAGE=6 -> 96KB

    cudaFuncSetAttribute((const void*)gemm_mma<3, 1, 3>,
                         cudaFuncAttributeMaxDynamicSharedMemorySize, SM_QK);
    cudaFuncSetAttribute((const void*)gemm_mma<2, 1, 4>,
                         cudaFuncAttributeMaxDynamicSharedMemorySize, SM_V);
    cudaFuncSetAttribute((const void*)gemm_mma<1, 1, 6>,
                         cudaFuncAttributeMaxDynamicSharedMemorySize, SM_PV);

    // ---- prologue splits ----
    split_kernel<<<(SEQ * DIM / 4 + 255) / 256, 256>>>(x, xh, xl, SEQ * DIM / 4);
    {
        TArgs ta = {};
        ta.in[0] = WQ;  ta.in[1] = WK;  ta.in[2] = WV;
        ta.hiT[0] = wqh; ta.hiT[1] = wkh; ta.hiT[2] = wvh;
        ta.loT[0] = wql; ta.loT[1] = wkl; ta.loT[2] = wvl;
        dim3 gT(DIM / 32, DIM / 32, 3);
        splitT3_kernel<<<gT, 256>>>(ta, DIM, DIM);
    }

    // ---- Q,K projections (z-fused, 3-term, compile-time) ----
    {
        GArgs ga = {};
        for (int z = 0; z < 2; z++) { ga.A1[z] = xh; ga.A2[z] = xl; }
        ga.B1[0] = wqh; ga.B2[0] = wql;
        ga.B1[1] = wkh; ga.B2[1] = wkl;
        ga.bias[0] = bQ; ga.bias[1] = bK;
        ga.Ch[0] = qh; ga.Cl[0] = ql;
        ga.Ch[1] = kh; ga.Cl[1] = kl;
        ga.epi[0] = EPI_SPLIT; ga.epi[1] = EPI_SPLIT;
        ga.N[0] = DIM; ga.N[1] = DIM;
        ga.alpha[0] = 1.0f; ga.alpha[1] = 1.0f;
        ga.K = DIM; ga.ldct = 0;
        dim3 g(DIM / 128, SEQ / 128, 2);
        gemm_mma<3, 1, 3><<<g, 128, SM_QK>>>(ga);
    }

    // ---- V projection (2-term, 4-stage pipeline) -> V^T fp16 ----
    {
        GArgs ga = {};
        ga.A1[0] = xh;
        ga.B1[0] = wvh; ga.B2[0] = wvl;
        ga.bias[0] = bV;
        ga.Ch[0] = vth;
        ga.epi[0] = EPI_H_T;
        ga.N[0] = DIM;
        ga.alpha[0] = 1.0f;
        ga.K = DIM; ga.ldct = SEQ;
        dim3 g(DIM / 128, SEQ / 128, 1);
        gemm_mma<2, 1, 4><<<g, 128, SM_V>>>(ga);
    }

    // ---- scores: S = (Q @ K^T) / 32 (3-term, byte-identical schedule) ----
    {
        GArgs ga = {};
        ga.A1[0] = qh; ga.A2[0] = ql;
        ga.B1[0] = kh; ga.B2[0] = kl;
        ga.Cf[0] = S; ga.epi[0] = EPI_F32;
        ga.N[0] = SEQ; ga.alpha[0] = 0.03125f;
        ga.K = DIM; ga.ldct = 0;
        dim3 g(SEQ / 128, SEQ / 128, 1);
        gemm_mma<3, 1, 3><<<g, 128, SM_QK>>>(ga);
    }

    // ---- softmax (polynomial exp) ----
    softmax_reg<<<SEQ, 256>>>(S, ph, SEQ);

    // ---- PV: out = P @ V (1-term, 6-stage pipeline) ----
    {
        GArgs ga = {};
        ga.A1[0] = ph;
        ga.B1[0] = vth;
        ga.Cf[0] = out; ga.epi[0] = EPI_F32;
        ga.N[0] = DIM; ga.alpha[0] = 1.0f;
        ga.K = SEQ; ga.ldct = 0;
        dim3 g(DIM / 128, SEQ / 128, 1);
        gemm_mma<1, 1, 6><<<g, 128, SM_PV>>>(ga);
    }
}